// round 1
// baseline (speedup 1.0000x reference)
#include <cuda_runtime.h>

#define IN_F   4096
#define OUT_F  11008
#define NC     16
#define TOPK   1024
#define NTH    1024   // prep kernel threads (each owns 4 contiguous elements)

__device__ float g_xmask[IN_F];

// ---------------------------------------------------------------------------
// Kernel 1: softmax(|x|) -> nearest cluster -> exact top-1024 mask of x
// Single block, 1024 threads. All data fits in shared.
// ---------------------------------------------------------------------------
__global__ void __launch_bounds__(NTH)
prep_kernel(const float* __restrict__ x,
            const float* __restrict__ centers)
{
    __shared__ float    s_act[IN_F];     // softmax activations
    __shared__ unsigned s_keys[IN_F];    // chosen-center values as order-preserving bits
    __shared__ float    s_red[32];
    __shared__ unsigned s_hist[256];
    __shared__ int      s_ints[3];       // [0]=ci  [1]=remaining  [2]=prefix(key bits)
    __shared__ int      s_warp[32];
    __shared__ float    s_d2[NC];

    const int tid  = threadIdx.x;
    const int lane = tid & 31;
    const int wid  = tid >> 5;
    const int base = tid * 4;

    // ---- 1. a = |x| (mean over 1 row == identity), block max ----
    float a[4];
    float m = -1e30f;
#pragma unroll
    for (int j = 0; j < 4; j++) { a[j] = fabsf(x[base + j]); m = fmaxf(m, a[j]); }
#pragma unroll
    for (int o = 16; o > 0; o >>= 1) m = fmaxf(m, __shfl_xor_sync(0xffffffffu, m, o));
    if (lane == 0) s_red[wid] = m;
    __syncthreads();
    if (wid == 0) {
        float r = s_red[lane];
#pragma unroll
        for (int o = 16; o > 0; o >>= 1) r = fmaxf(r, __shfl_xor_sync(0xffffffffu, r, o));
        if (lane == 0) s_red[0] = r;
    }
    __syncthreads();
    m = s_red[0];
    __syncthreads();

    // ---- 2. softmax: exp(a-m), sum, normalize ----
    float s = 0.f;
#pragma unroll
    for (int j = 0; j < 4; j++) {
        float e = expf(a[j] - m);
        s_act[base + j] = e;
        s += e;
    }
#pragma unroll
    for (int o = 16; o > 0; o >>= 1) s += __shfl_xor_sync(0xffffffffu, s, o);
    if (lane == 0) s_red[wid] = s;
    __syncthreads();
    if (wid == 0) {
        float r = s_red[lane];
#pragma unroll
        for (int o = 16; o > 0; o >>= 1) r += __shfl_xor_sync(0xffffffffu, r, o);
        if (lane == 0) s_red[0] = r;
    }
    __syncthreads();
    const float inv_s = 1.f / s_red[0];
    __syncthreads();
#pragma unroll
    for (int j = 0; j < 4; j++) s_act[base + j] *= inv_s;
    __syncthreads();

    // ---- 3. squared distances to 16 centers, argmin ----
    for (int c = 0; c < NC; c++) {
        float local = 0.f;
        const float* cr = centers + (size_t)c * IN_F;
#pragma unroll
        for (int j = 0; j < 4; j++) {
            float d = cr[base + j] - s_act[base + j];
            local += d * d;
        }
#pragma unroll
        for (int o = 16; o > 0; o >>= 1) local += __shfl_xor_sync(0xffffffffu, local, o);
        if (lane == 0) s_red[wid] = local;
        __syncthreads();
        if (wid == 0) {
            float r = s_red[lane];
#pragma unroll
            for (int o = 16; o > 0; o >>= 1) r += __shfl_xor_sync(0xffffffffu, r, o);
            if (lane == 0) s_d2[c] = r;
        }
        __syncthreads();
    }
    if (tid == 0) {
        int   best = 0;
        float bv   = s_d2[0];
        for (int c = 1; c < NC; c++)
            if (s_d2[c] < bv) { bv = s_d2[c]; best = c; }   // first-min tie-break (jnp.argmin)
        s_ints[0] = best;
    }
    __syncthreads();

    // ---- 4. keys = bits of chosen center (positive floats -> monotone uint) ----
    const int ci = s_ints[0];
    const float* crow = centers + (size_t)ci * IN_F;
#pragma unroll
    for (int j = 0; j < 4; j++)
        s_keys[base + j] = __float_as_uint(crow[base + j]);
    __syncthreads();

    // ---- 5. radix-select threshold T = TOPK-th largest key ----
    unsigned prefix    = 0;
    int      remaining = TOPK;
    for (int shift = 24; shift >= 0; shift -= 8) {
        if (tid < 256) s_hist[tid] = 0u;
        __syncthreads();
#pragma unroll
        for (int j = 0; j < 4; j++) {
            unsigned key = s_keys[base + j];
            bool match = (shift == 24) ||
                         ((key >> (shift + 8)) == (prefix >> (shift + 8)));
            if (match) atomicAdd(&s_hist[(key >> shift) & 255u], 1u);
        }
        __syncthreads();
        // inclusive suffix scan over 256 bins: hist[b] := #elements with byte >= b
        for (int off = 1; off < 256; off <<= 1) {
            unsigned v = 0;
            if (tid < 256)
                v = s_hist[tid] + ((tid + off < 256) ? s_hist[tid + off] : 0u);
            __syncthreads();
            if (tid < 256) s_hist[tid] = v;
            __syncthreads();
        }
        if (tid < 256) {
            int ge = (int)s_hist[tid];
            int gt = (tid < 255) ? (int)s_hist[tid + 1] : 0;
            if (ge >= remaining && gt < remaining) {       // unique crossing bin
                s_ints[1] = remaining - gt;                // ties still needed
                s_ints[2] = (int)(prefix | ((unsigned)tid << shift));
            }
        }
        __syncthreads();
        remaining = s_ints[1];
        prefix    = (unsigned)s_ints[2];
        __syncthreads();
    }
    const unsigned T = prefix;
    const int      R = remaining;   // take the R lowest-index ties (jax top_k order)

    // ---- 6. tie-rank prefix scan (index order) + write masked x ----
    int cnt[4];
    int tot = 0;
#pragma unroll
    for (int j = 0; j < 4; j++) {
        cnt[j] = tot;
        tot += (s_keys[base + j] == T) ? 1 : 0;
    }
    int incl = tot;
#pragma unroll
    for (int off = 1; off < 32; off <<= 1) {
        int n = __shfl_up_sync(0xffffffffu, incl, off);
        if (lane >= off) incl += n;
    }
    if (lane == 31) s_warp[wid] = incl;
    __syncthreads();
    if (wid == 0) {
        int v = s_warp[lane];
#pragma unroll
        for (int off = 1; off < 32; off <<= 1) {
            int n = __shfl_up_sync(0xffffffffu, v, off);
            if (lane >= off) v += n;
        }
        s_warp[lane] = v;
    }
    __syncthreads();
    const int excl = incl - tot + (wid > 0 ? s_warp[wid - 1] : 0);
#pragma unroll
    for (int j = 0; j < 4; j++) {
        const int i = base + j;
        unsigned key = s_keys[i];
        bool sel = (key > T) || (key == T && (excl + cnt[j]) < R);
        g_xmask[i] = sel ? x[i] : 0.f;
    }
}

// ---------------------------------------------------------------------------
// Kernel 2: out = W @ x_masked + bias   (HBM-streaming dense matvec)
// 256 threads/block = 8 warps = 8 rows/block, float4 loads, warp reduction.
// ---------------------------------------------------------------------------
__global__ void __launch_bounds__(256)
matvec_kernel(const float* __restrict__ W,
              const float* __restrict__ bias,
              float* __restrict__ out)
{
    __shared__ float4 sx[IN_F / 4];
    const int tid = threadIdx.x;
    for (int i = tid; i < IN_F / 4; i += 256)
        sx[i] = reinterpret_cast<const float4*>(g_xmask)[i];
    __syncthreads();

    const int warp = tid >> 5;
    const int lane = tid & 31;
    const int row  = blockIdx.x * 8 + warp;
    if (row >= OUT_F) return;

    const float4* wr = reinterpret_cast<const float4*>(W + (size_t)row * IN_F);
    float acc = 0.f;
#pragma unroll 8
    for (int j = lane; j < IN_F / 4; j += 32) {
        float4 w  = wr[j];
        float4 xv = sx[j];
        acc += w.x * xv.x + w.y * xv.y + w.z * xv.z + w.w * xv.w;
    }
#pragma unroll
    for (int o = 16; o > 0; o >>= 1)
        acc += __shfl_xor_sync(0xffffffffu, acc, o);
    if (lane == 0)
        out[row] = acc + bias[row];
}

// ---------------------------------------------------------------------------
extern "C" void kernel_launch(void* const* d_in, const int* in_sizes, int n_in,
                              void* d_out, int out_size)
{
    const float* x       = (const float*)d_in[0];  // [4096]
    const float* weight  = (const float*)d_in[1];  // [11008, 4096]
    const float* bias    = (const float*)d_in[2];  // [11008]
    const float* centers = (const float*)d_in[3];  // [16, 4096]
    float*       out     = (float*)d_out;          // [11008]

    prep_kernel<<<1, NTH>>>(x, centers);
    matvec_kernel<<<(OUT_F + 7) / 8, 256>>>(weight, bias, out);
}

// round 2
// speedup vs baseline: 1.2809x; 1.2809x over previous
#include <cuda_runtime.h>

#define IN_F   4096
#define OUT_F  11008
#define NC     16
#define TOPK   1024

__device__ float g_xmask[IN_F];

// ---------------------------------------------------------------------------
// Kernel 1: softmax(|x|) -> nearest cluster -> exact top-1024 mask of x
// Single block, 1024 threads.
// ---------------------------------------------------------------------------
__global__ void __launch_bounds__(1024)
prep_kernel(const float* __restrict__ x,
            const float* __restrict__ centers)
{
    __shared__ __align__(16) float s_act[IN_F];   // softmax activations
    __shared__ unsigned s_keys[IN_F];             // chosen-center bits (order-preserving)
    __shared__ float    s_red[32];
    __shared__ unsigned s_hist[4][256];           // one histogram per radix pass
    __shared__ unsigned s_wsum[8];
    __shared__ int      s_ints[3];                // [0]=ci [1]=remaining [2]=prefix
    __shared__ int      s_warp[32];
    __shared__ float    s_d2p[32];                // per-warp distance partials

    const int tid  = threadIdx.x;
    const int lane = tid & 31;
    const int wid  = tid >> 5;
    const int base = tid * 4;

    // clear all 4 histograms up front: 4*256 = 1024 entries, one per thread
    ((unsigned*)s_hist)[tid] = 0u;

    // ---- 1. a = |x|, block max ----
    const float4 xv4 = reinterpret_cast<const float4*>(x)[tid];
    float a[4] = { fabsf(xv4.x), fabsf(xv4.y), fabsf(xv4.z), fabsf(xv4.w) };
    float m = fmaxf(fmaxf(a[0], a[1]), fmaxf(a[2], a[3]));
#pragma unroll
    for (int o = 16; o > 0; o >>= 1) m = fmaxf(m, __shfl_xor_sync(0xffffffffu, m, o));
    if (lane == 0) s_red[wid] = m;
    __syncthreads();
    if (wid == 0) {
        float r = s_red[lane];
#pragma unroll
        for (int o = 16; o > 0; o >>= 1) r = fmaxf(r, __shfl_xor_sync(0xffffffffu, r, o));
        if (lane == 0) s_red[0] = r;
    }
    __syncthreads();
    m = s_red[0];
    __syncthreads();   // everyone done reading s_red[0] before reuse

    // ---- 2. softmax ----
    float e[4];
    float s = 0.f;
#pragma unroll
    for (int j = 0; j < 4; j++) { e[j] = expf(a[j] - m); s += e[j]; }
#pragma unroll
    for (int o = 16; o > 0; o >>= 1) s += __shfl_xor_sync(0xffffffffu, s, o);
    if (lane == 0) s_red[wid] = s;
    __syncthreads();
    if (wid == 0) {
        float r = s_red[lane];
#pragma unroll
        for (int o = 16; o > 0; o >>= 1) r += __shfl_xor_sync(0xffffffffu, r, o);
        if (lane == 0) s_red[0] = r;
    }
    __syncthreads();
    const float inv_s = 1.f / s_red[0];
#pragma unroll
    for (int j = 0; j < 4; j++) s_act[base + j] = e[j] * inv_s;
    __syncthreads();

    // ---- 3. squared distances: 2 warps per center, one parallel pass ----
    {
        const int c    = wid >> 1;          // center 0..15
        const int half = wid & 1;           // which 2048-element half
        const float4* cc = reinterpret_cast<const float4*>(centers) + c * 1024 + half * 512;
        const float4* sa = reinterpret_cast<const float4*>(s_act) + half * 512;
        float local = 0.f;
#pragma unroll
        for (int k = 0; k < 16; k++) {
            const int idx = k * 32 + lane;
            float4 cv = cc[idx];
            float4 av = sa[idx];
            float dx = cv.x - av.x, dy = cv.y - av.y;
            float dz = cv.z - av.z, dw = cv.w - av.w;
            local += dx * dx + dy * dy + dz * dz + dw * dw;
        }
#pragma unroll
        for (int o = 16; o > 0; o >>= 1) local += __shfl_xor_sync(0xffffffffu, local, o);
        if (lane == 0) s_d2p[wid] = local;
    }
    __syncthreads();
    if (tid == 0) {
        int best = 0;
        float bv = s_d2p[0] + s_d2p[1];
        for (int c = 1; c < NC; c++) {
            float v = s_d2p[2 * c] + s_d2p[2 * c + 1];
            if (v < bv) { bv = v; best = c; }          // first-min tie-break
        }
        s_ints[0] = best;
    }
    __syncthreads();

    // ---- 4. keys = bits of chosen center ----
    {
        const int ci = s_ints[0];
        const float4 cv = reinterpret_cast<const float4*>(centers)[ci * 1024 + tid];
        s_keys[base + 0] = __float_as_uint(cv.x);
        s_keys[base + 1] = __float_as_uint(cv.y);
        s_keys[base + 2] = __float_as_uint(cv.z);
        s_keys[base + 3] = __float_as_uint(cv.w);
    }
    __syncthreads();

    // ---- 5. radix-select threshold T = TOPK-th largest key ----
    unsigned prefix    = 0;
    int      remaining = TOPK;
#pragma unroll
    for (int p = 0; p < 4; p++) {
        const int shift = 24 - 8 * p;
        // histogram of matching keys
#pragma unroll
        for (int j = 0; j < 4; j++) {
            unsigned key = s_keys[base + j];
            bool match = (p == 0) ||
                         ((key >> (shift + 8)) == (prefix >> (shift + 8)));
            if (match) atomicAdd(&s_hist[p][(key >> shift) & 255u], 1u);
        }
        __syncthreads();
        // suffix scan over 256 bins: warp-shuffle within 8 warps of tid<256
        unsigned v = 0, cnt = 0;
        if (tid < 256) {
            cnt = s_hist[p][tid];
            v = cnt;
#pragma unroll
            for (int off = 1; off < 32; off <<= 1) {
                unsigned n = __shfl_down_sync(0xffffffffu, v, off);
                if (lane + off < 32) v += n;
            }
            if (lane == 0) s_wsum[wid] = v;   // warp total (sum of its 32 bins)
        }
        __syncthreads();
        if (tid < 256) {
            unsigned off = 0;
            for (int w2 = wid + 1; w2 < 8; w2++) off += s_wsum[w2];
            unsigned ge = v + off;            // #keys with byte >= tid (among matching)
            unsigned gt = ge - cnt;           // #keys with byte >  tid
            if ((int)ge >= remaining && (int)gt < remaining) {   // unique crossing bin
                s_ints[1] = remaining - (int)gt;
                s_ints[2] = (int)(prefix | ((unsigned)tid << shift));
            }
        }
        __syncthreads();
        remaining = s_ints[1];
        prefix    = (unsigned)s_ints[2];
        __syncthreads();
    }
    const unsigned T = prefix;
    const int      R = remaining;   // take the R lowest-index ties (jax top_k order)

    // ---- 6. tie-rank prefix scan (index order) + write masked x ----
    int cnt4[4];
    int tot = 0;
#pragma unroll
    for (int j = 0; j < 4; j++) {
        cnt4[j] = tot;
        tot += (s_keys[base + j] == T) ? 1 : 0;
    }
    int incl = tot;
#pragma unroll
    for (int off = 1; off < 32; off <<= 1) {
        int n = __shfl_up_sync(0xffffffffu, incl, off);
        if (lane >= off) incl += n;
    }
    if (lane == 31) s_warp[wid] = incl;
    __syncthreads();
    if (wid == 0) {
        int v = s_warp[lane];
#pragma unroll
        for (int off = 1; off < 32; off <<= 1) {
            int n = __shfl_up_sync(0xffffffffu, v, off);
            if (lane >= off) v += n;
        }
        s_warp[lane] = v;
    }
    __syncthreads();
    const int excl = incl - tot + (wid > 0 ? s_warp[wid - 1] : 0);
    const float xin[4] = { xv4.x, xv4.y, xv4.z, xv4.w };
#pragma unroll
    for (int j = 0; j < 4; j++) {
        unsigned key = s_keys[base + j];
        bool sel = (key > T) || (key == T && (excl + cnt4[j]) < R);
        g_xmask[base + j] = sel ? xin[j] : 0.f;
    }
}

// ---------------------------------------------------------------------------
// Kernel 2: out = W @ x_masked + bias   (HBM-streaming dense matvec)
// 256 threads = 8 warps, 2 rows per warp (16 rows/block), float4 __ldcs loads.
// ---------------------------------------------------------------------------
__global__ void __launch_bounds__(256)
matvec_kernel(const float* __restrict__ W,
              const float* __restrict__ bias,
              float* __restrict__ out)
{
    __shared__ float4 sx[IN_F / 4];
    const int tid = threadIdx.x;
    for (int i = tid; i < IN_F / 4; i += 256)
        sx[i] = reinterpret_cast<const float4*>(g_xmask)[i];
    __syncthreads();

    const int warp = tid >> 5;
    const int lane = tid & 31;
    const int row0 = blockIdx.x * 16 + warp * 2;   // 11008 = 688 * 16, always in range

    const float4* w0 = reinterpret_cast<const float4*>(W + (size_t)row0 * IN_F);
    const float4* w1 = w0 + (IN_F / 4);

    float acc0 = 0.f, acc1 = 0.f;
#pragma unroll 4
    for (int j = lane; j < IN_F / 4; j += 32) {
        float4 wa = __ldcs(w0 + j);
        float4 wb = __ldcs(w1 + j);
        float4 xv = sx[j];
        acc0 += wa.x * xv.x + wa.y * xv.y + wa.z * xv.z + wa.w * xv.w;
        acc1 += wb.x * xv.x + wb.y * xv.y + wb.z * xv.z + wb.w * xv.w;
    }
#pragma unroll
    for (int o = 16; o > 0; o >>= 1) {
        acc0 += __shfl_xor_sync(0xffffffffu, acc0, o);
        acc1 += __shfl_xor_sync(0xffffffffu, acc1, o);
    }
    if (lane == 0) {
        out[row0]     = acc0 + bias[row0];
        out[row0 + 1] = acc1 + bias[row0 + 1];
    }
}

// ---------------------------------------------------------------------------
extern "C" void kernel_launch(void* const* d_in, const int* in_sizes, int n_in,
                              void* d_out, int out_size)
{
    const float* x       = (const float*)d_in[0];  // [4096]
    const float* weight  = (const float*)d_in[1];  // [11008, 4096]
    const float* bias    = (const float*)d_in[2];  // [11008]
    const float* centers = (const float*)d_in[3];  // [16, 4096]
    float*       out     = (float*)d_out;          // [11008]

    prep_kernel<<<1, 1024>>>(x, centers);
    matvec_kernel<<<OUT_F / 16, 256>>>(weight, bias, out);
}

// round 3
// speedup vs baseline: 1.3428x; 1.0483x over previous
#include <cuda_runtime.h>

#define IN_F   4096
#define OUT_F  11008
#define NC     16
#define TOPK   1024

__device__ float g_xmask[IN_F];
__device__ float g_d2[NC];

// ---------------------------------------------------------------------------
// Kernel 1: one block per center. Each block redundantly computes
// softmax(|x|) (identical, deterministic) then d2 to its center.
// 256 threads, 16 elements each.
// ---------------------------------------------------------------------------
__global__ void __launch_bounds__(256)
distc_kernel(const float* __restrict__ x,
             const float* __restrict__ centers)
{
    __shared__ float s_red[8];
    __shared__ float s_b;

    const int tid  = threadIdx.x;
    const int lane = tid & 31;
    const int wid  = tid >> 5;
    const int c    = blockIdx.x;

    const float4* X4 = reinterpret_cast<const float4*>(x);

    // |x|, local max
    float a[16];
    float m = -1e30f;
#pragma unroll
    for (int k = 0; k < 4; k++) {
        float4 v = X4[tid + 256 * k];
        a[4 * k + 0] = fabsf(v.x); a[4 * k + 1] = fabsf(v.y);
        a[4 * k + 2] = fabsf(v.z); a[4 * k + 3] = fabsf(v.w);
        m = fmaxf(m, fmaxf(fmaxf(a[4*k], a[4*k+1]), fmaxf(a[4*k+2], a[4*k+3])));
    }
#pragma unroll
    for (int o = 16; o > 0; o >>= 1) m = fmaxf(m, __shfl_xor_sync(0xffffffffu, m, o));
    if (lane == 0) s_red[wid] = m;
    __syncthreads();
    if (tid == 0) {
        float r = s_red[0];
#pragma unroll
        for (int w = 1; w < 8; w++) r = fmaxf(r, s_red[w]);
        s_b = r;
    }
    __syncthreads();
    m = s_b;
    __syncthreads();

    // exp + sum
    float e[16];
    float s = 0.f;
#pragma unroll
    for (int k = 0; k < 16; k++) { e[k] = expf(a[k] - m); s += e[k]; }
#pragma unroll
    for (int o = 16; o > 0; o >>= 1) s += __shfl_xor_sync(0xffffffffu, s, o);
    if (lane == 0) s_red[wid] = s;
    __syncthreads();
    if (tid == 0) {
        float r = 0.f;
#pragma unroll
        for (int w = 0; w < 8; w++) r += s_red[w];
        s_b = r;
    }
    __syncthreads();
    const float inv_s = 1.f / s_b;
    __syncthreads();

    // squared distance to center c
    const float4* C4 = reinterpret_cast<const float4*>(centers) + c * (IN_F / 4);
    float d2 = 0.f;
#pragma unroll
    for (int k = 0; k < 4; k++) {
        float4 cv = C4[tid + 256 * k];
        float dx = cv.x - e[4*k+0] * inv_s;
        float dy = cv.y - e[4*k+1] * inv_s;
        float dz = cv.z - e[4*k+2] * inv_s;
        float dw = cv.w - e[4*k+3] * inv_s;
        d2 += dx * dx + dy * dy + dz * dz + dw * dw;
    }
#pragma unroll
    for (int o = 16; o > 0; o >>= 1) d2 += __shfl_xor_sync(0xffffffffu, d2, o);
    if (lane == 0) s_red[wid] = d2;
    __syncthreads();
    if (tid == 0) {
        float r = 0.f;
#pragma unroll
        for (int w = 0; w < 8; w++) r += s_red[w];
        g_d2[c] = r;
    }
}

// ---------------------------------------------------------------------------
// Kernel 2: argmin over g_d2, exact top-1024 radix select on chosen center,
// write masked x. Single block, 1024 threads.
// ---------------------------------------------------------------------------
__global__ void __launch_bounds__(1024)
select_kernel(const float* __restrict__ x,
              const float* __restrict__ centers)
{
    __shared__ unsigned s_keys[IN_F];
    __shared__ unsigned s_hist[4][256];
    __shared__ unsigned s_wsum[8];
    __shared__ int      s_ints[3];   // [0]=ci [1]=remaining [2]=prefix
    __shared__ int      s_warp[32];

    const int tid  = threadIdx.x;
    const int lane = tid & 31;
    const int wid  = tid >> 5;
    const int base = tid * 4;

    ((unsigned*)s_hist)[tid] = 0u;   // clear all 4 histograms (1 entry/thread)

    if (tid == 0) {
        int best = 0;
        float bv = g_d2[0];
        for (int c = 1; c < NC; c++)
            if (g_d2[c] < bv) { bv = g_d2[c]; best = c; }   // first-min tie-break
        s_ints[0] = best;
    }
    const float4 xv4 = reinterpret_cast<const float4*>(x)[tid];
    __syncthreads();

    // keys = bits of chosen center (positive floats -> monotone uint)
    {
        const int ci = s_ints[0];
        const float4 cv = reinterpret_cast<const float4*>(centers)[ci * (IN_F / 4) + tid];
        s_keys[base + 0] = __float_as_uint(cv.x);
        s_keys[base + 1] = __float_as_uint(cv.y);
        s_keys[base + 2] = __float_as_uint(cv.z);
        s_keys[base + 3] = __float_as_uint(cv.w);
    }
    __syncthreads();

    // radix-select threshold T = TOPK-th largest key
    unsigned prefix    = 0;
    int      remaining = TOPK;
#pragma unroll
    for (int p = 0; p < 4; p++) {
        const int shift = 24 - 8 * p;
#pragma unroll
        for (int j = 0; j < 4; j++) {
            unsigned key = s_keys[base + j];
            bool match = (p == 0) ||
                         ((key >> (shift + 8)) == (prefix >> (shift + 8)));
            if (match) atomicAdd(&s_hist[p][(key >> shift) & 255u], 1u);
        }
        __syncthreads();
        unsigned v = 0, cnt = 0;
        if (tid < 256) {
            cnt = s_hist[p][tid];
            v = cnt;
#pragma unroll
            for (int off = 1; off < 32; off <<= 1) {
                unsigned n = __shfl_down_sync(0xffffffffu, v, off);
                if (lane + off < 32) v += n;
            }
            if (lane == 0) s_wsum[wid] = v;
        }
        __syncthreads();
        if (tid < 256) {
            unsigned off = 0;
            for (int w2 = wid + 1; w2 < 8; w2++) off += s_wsum[w2];
            unsigned ge = v + off;           // #keys with byte >= tid (among matching)
            unsigned gt = ge - cnt;          // #keys with byte >  tid
            if ((int)ge >= remaining && (int)gt < remaining) {   // unique crossing bin
                s_ints[1] = remaining - (int)gt;
                s_ints[2] = (int)(prefix | ((unsigned)tid << shift));
            }
        }
        __syncthreads();
        remaining = s_ints[1];
        prefix    = (unsigned)s_ints[2];
        __syncthreads();
    }
    const unsigned T = prefix;
    const int      R = remaining;   // take the R lowest-index ties (jax top_k order)

    // tie-rank prefix scan (index order) + write masked x
    int cnt4[4];
    int tot = 0;
#pragma unroll
    for (int j = 0; j < 4; j++) {
        cnt4[j] = tot;
        tot += (s_keys[base + j] == T) ? 1 : 0;
    }
    int incl = tot;
#pragma unroll
    for (int off = 1; off < 32; off <<= 1) {
        int n = __shfl_up_sync(0xffffffffu, incl, off);
        if (lane >= off) incl += n;
    }
    if (lane == 31) s_warp[wid] = incl;
    __syncthreads();
    if (wid == 0) {
        int v = s_warp[lane];
#pragma unroll
        for (int off = 1; off < 32; off <<= 1) {
            int n = __shfl_up_sync(0xffffffffu, v, off);
            if (lane >= off) v += n;
        }
        s_warp[lane] = v;
    }
    __syncthreads();
    const int excl = incl - tot + (wid > 0 ? s_warp[wid - 1] : 0);
    const float xin[4] = { xv4.x, xv4.y, xv4.z, xv4.w };
    float o4[4];
#pragma unroll
    for (int j = 0; j < 4; j++) {
        unsigned key = s_keys[base + j];
        bool sel = (key > T) || (key == T && (excl + cnt4[j]) < R);
        o4[j] = sel ? xin[j] : 0.f;
    }
    reinterpret_cast<float4*>(g_xmask)[tid] = make_float4(o4[0], o4[1], o4[2], o4[3]);
}

// ---------------------------------------------------------------------------
// Kernel 3: out = W @ x_masked + bias   (HBM-streaming dense matvec)
// 256 threads = 8 warps, 1 row/warp, grid=1376. Dual accumulator streams.
// ---------------------------------------------------------------------------
__global__ void __launch_bounds__(256)
matvec_kernel(const float* __restrict__ W,
              const float* __restrict__ bias,
              float* __restrict__ out)
{
    __shared__ float4 sx[IN_F / 4];
    const int tid = threadIdx.x;
    for (int i = tid; i < IN_F / 4; i += 256)
        sx[i] = reinterpret_cast<const float4*>(g_xmask)[i];
    __syncthreads();

    const int warp = tid >> 5;
    const int lane = tid & 31;
    const int row  = blockIdx.x * 8 + warp;   // 11008 = 1376 * 8, always in range

    const float4* wr = reinterpret_cast<const float4*>(W + (size_t)row * IN_F);

    float acc0 = 0.f, acc1 = 0.f;
#pragma unroll 4
    for (int j = lane; j < IN_F / 4; j += 64) {
        float4 wa = wr[j];
        float4 wb = wr[j + 32];
        float4 xa = sx[j];
        float4 xb = sx[j + 32];
        acc0 += wa.x * xa.x + wa.y * xa.y + wa.z * xa.z + wa.w * xa.w;
        acc1 += wb.x * xb.x + wb.y * xb.y + wb.z * xb.z + wb.w * xb.w;
    }
    float acc = acc0 + acc1;
#pragma unroll
    for (int o = 16; o > 0; o >>= 1)
        acc += __shfl_xor_sync(0xffffffffu, acc, o);
    if (lane == 0)
        out[row] = acc + bias[row];
}

// ---------------------------------------------------------------------------
extern "C" void kernel_launch(void* const* d_in, const int* in_sizes, int n_in,
                              void* d_out, int out_size)
{
    const float* x       = (const float*)d_in[0];  // [4096]
    const float* weight  = (const float*)d_in[1];  // [11008, 4096]
    const float* bias    = (const float*)d_in[2];  // [11008]
    const float* centers = (const float*)d_in[3];  // [16, 4096]
    float*       out     = (float*)d_out;          // [11008]

    distc_kernel<<<NC, 256>>>(x, centers);
    select_kernel<<<1, 1024>>>(x, centers);
    matvec_kernel<<<OUT_F / 8, 256>>>(weight, bias, out);
}